// round 3
// baseline (speedup 1.0000x reference)
#include <cuda_runtime.h>

#define NN   50000
#define EE   800000
#define INC  32
#define HIDC 64

// Scratch (device globals — zero-initialized at module load).
// Invariant: g_agg1 and g_deg are ZERO at entry of every kernel_launch call
// (k_layer2 restores them at the end of each call). g_agg2 is zeroed by
// k_layer1 before k_scatter2 uses it.
__device__ __align__(16) float g_deg[NN];
__device__ __align__(16) float g_agg1[NN * INC];
__device__ __align__(16) float g_agg2[NN * HIDC];
__device__ __align__(16) float g_h[NN * HIDC];

__device__ __forceinline__ void red_add_v4(float* p, float4 v) {
    asm volatile("red.global.add.v4.f32 [%0], {%1,%2,%3,%4};"
                 :: "l"(p), "f"(v.x), "f"(v.y), "f"(v.z), "f"(v.w)
                 : "memory");
}

// ---------------------------------------------------------------------------
// Scatter 1: agg1[dst, 0:32] += x[src, 0:32]; deg[dst] += 1
// 2 threads per edge, 16 channels (4 x float4) each.
// ---------------------------------------------------------------------------
__global__ __launch_bounds__(256)
void k_scatter1(const float* __restrict__ x,
                const int* __restrict__ src,
                const int* __restrict__ dst) {
    int idx = blockIdx.x * blockDim.x + threadIdx.x;
    if (idx >= EE * 2) return;
    int e = idx >> 1;
    int q = idx & 1;
    int s = __ldg(&src[e]);
    int d = __ldg(&dst[e]);
    const float4* xs = (const float4*)x + (long long)s * 8 + q * 4;
    float* ad = &g_agg1[(long long)d * INC + q * 16];
    float4 v0 = __ldg(xs + 0);
    float4 v1 = __ldg(xs + 1);
    float4 v2 = __ldg(xs + 2);
    float4 v3 = __ldg(xs + 3);
    red_add_v4(ad + 0,  v0);
    red_add_v4(ad + 4,  v1);
    red_add_v4(ad + 8,  v2);
    red_add_v4(ad + 12, v3);
    if (q == 0) atomicAdd(&g_deg[d], 1.0f);
}

// ---------------------------------------------------------------------------
// Layer 1: h = relu( bn1( (agg1*deg_inv) @ W1l + b1l + x @ W1r ) )
// 2 threads per node; thread q computes outputs [q*32, q*32+32).
// Also zeroes this node's g_agg2 half-row for scatter2.
// BN folded: alpha = g*rsqrt(v+eps); beta = (b1l - m)*alpha + bn_b
// ---------------------------------------------------------------------------
__global__ __launch_bounds__(256)
void k_layer1(const float* __restrict__ x,
              const float* __restrict__ W1l, const float* __restrict__ b1l,
              const float* __restrict__ W1r,
              const float* __restrict__ g1, const float* __restrict__ bb1,
              const float* __restrict__ m1, const float* __restrict__ v1) {
    __shared__ float swl[HIDC * INC];   // [o][i]
    __shared__ float swr[HIDC * INC];
    __shared__ float alpha[HIDC], beta[HIDC];

    int tid = threadIdx.x;
    for (int t = tid; t < HIDC * INC; t += blockDim.x) {
        int o = t >> 5, i = t & 31;
        swl[t] = W1l[i * HIDC + o];
        swr[t] = W1r[i * HIDC + o];
    }
    if (tid < HIDC) {
        float a = g1[tid] * rsqrtf(v1[tid] + 1e-5f);
        alpha[tid] = a;
        beta[tid]  = (b1l[tid] - m1[tid]) * a + bb1[tid];
    }
    __syncthreads();

    int idx = blockIdx.x * blockDim.x + tid;
    if (idx >= NN * 2) return;
    int n = idx >> 1;
    int q = idx & 1;

    float dinv = 1.0f / fmaxf(g_deg[n], 1.0f);
    float a[INC], xr[INC];
    const float4* av = (const float4*)&g_agg1[(long long)n * INC];
    const float4* xv = (const float4*)&x[(long long)n * INC];
#pragma unroll
    for (int j = 0; j < 8; j++) {
        float4 t1 = av[j];
        a[4*j+0] = t1.x * dinv; a[4*j+1] = t1.y * dinv;
        a[4*j+2] = t1.z * dinv; a[4*j+3] = t1.w * dinv;
        float4 t2 = xv[j];
        xr[4*j+0] = t2.x; xr[4*j+1] = t2.y; xr[4*j+2] = t2.z; xr[4*j+3] = t2.w;
    }

    // Zero g_agg2 half-row (for scatter2, which runs after this kernel)
    float4* z = (float4*)&g_agg2[(long long)n * HIDC + q * 32];
#pragma unroll
    for (int j = 0; j < 8; j++) z[j] = make_float4(0.f, 0.f, 0.f, 0.f);

    float4* hv = (float4*)&g_h[(long long)n * HIDC] + q * 8;
    const float4* wl4 = (const float4*)swl;
    const float4* wr4 = (const float4*)swr;
    int obase = q * 32;

#pragma unroll 1
    for (int og = 0; og < 8; og++) {
        float res[4];
#pragma unroll
        for (int k = 0; k < 4; k++) {
            int o = obase + og * 4 + k;
            float acc = 0.f;
#pragma unroll
            for (int j = 0; j < 8; j++) {
                float4 wl = wl4[o * 8 + j];
                float4 wr = wr4[o * 8 + j];
                acc += a[4*j+0]*wl.x + a[4*j+1]*wl.y + a[4*j+2]*wl.z + a[4*j+3]*wl.w;
                acc += xr[4*j+0]*wr.x + xr[4*j+1]*wr.y + xr[4*j+2]*wr.z + xr[4*j+3]*wr.w;
            }
            res[k] = fmaxf(acc * alpha[o] + beta[o], 0.0f);
        }
        hv[og] = make_float4(res[0], res[1], res[2], res[3]);
    }
}

// ---------------------------------------------------------------------------
// Scatter 2: agg2[dst, 0:64] += h[src, 0:64]
// 4 threads per edge, 16 channels (4 x float4) each.
// ---------------------------------------------------------------------------
__global__ __launch_bounds__(256)
void k_scatter2(const int* __restrict__ src,
                const int* __restrict__ dst) {
    int idx = blockIdx.x * blockDim.x + threadIdx.x;
    if (idx >= EE * 4) return;
    int e = idx >> 2;
    int q = idx & 3;
    int s = __ldg(&src[e]);
    int d = __ldg(&dst[e]);
    const float4* hs = (const float4*)g_h + (long long)s * 16 + q * 4;
    float* ad = &g_agg2[(long long)d * HIDC + q * 16];
    float4 v0 = __ldg(hs + 0);
    float4 v1 = __ldg(hs + 1);
    float4 v2 = __ldg(hs + 2);
    float4 v3 = __ldg(hs + 3);
    red_add_v4(ad + 0,  v0);
    red_add_v4(ad + 4,  v1);
    red_add_v4(ad + 8,  v2);
    red_add_v4(ad + 12, v3);
}

// ---------------------------------------------------------------------------
// Layer 2 + head: h2 = relu(bn2((agg2*dinv)@W2l + b2l + h@W2r));
//                 out = h2 @ Wlin + blin
// 2 threads per node; thread q computes outputs [q*32, q*32+32), partial head
// sums combined via shfl. Also restores g_agg1/g_deg to zero for next call.
// ---------------------------------------------------------------------------
__global__ __launch_bounds__(256)
void k_layer2(const float* __restrict__ W2l, const float* __restrict__ b2l,
              const float* __restrict__ W2r,
              const float* __restrict__ g2, const float* __restrict__ bb2,
              const float* __restrict__ m2, const float* __restrict__ v2,
              const float* __restrict__ Wlin, const float* __restrict__ blin,
              float* __restrict__ out) {
    __shared__ float swl[HIDC * HIDC];   // [o][i] 16KB
    __shared__ float swr[HIDC * HIDC];   // 16KB
    __shared__ float alpha[HIDC], beta[HIDC], swo[HIDC];

    int tid = threadIdx.x;
    for (int t = tid; t < HIDC * HIDC; t += blockDim.x) {
        int o = t >> 6, i = t & 63;
        swl[t] = W2l[i * HIDC + o];
        swr[t] = W2r[i * HIDC + o];
    }
    if (tid < HIDC) {
        float a = g2[tid] * rsqrtf(v2[tid] + 1e-5f);
        alpha[tid] = a;
        beta[tid]  = (b2l[tid] - m2[tid]) * a + bb2[tid];
        swo[tid]   = Wlin[tid];
    }
    __syncthreads();

    int idx = blockIdx.x * blockDim.x + tid;
    if (idx >= NN * 2) return;
    int n = idx >> 1;
    int q = idx & 1;

    float dinv = 1.0f / fmaxf(g_deg[n], 1.0f);   // both pair-lanes read (convergent)
    float a[HIDC], hh[HIDC];
    const float4* av = (const float4*)&g_agg2[(long long)n * HIDC];
    const float4* hv = (const float4*)&g_h[(long long)n * HIDC];
#pragma unroll
    for (int j = 0; j < 16; j++) {
        float4 t1 = av[j];
        a[4*j+0] = t1.x * dinv; a[4*j+1] = t1.y * dinv;
        a[4*j+2] = t1.z * dinv; a[4*j+3] = t1.w * dinv;
        float4 t2 = hv[j];
        hh[4*j+0] = t2.x; hh[4*j+1] = t2.y; hh[4*j+2] = t2.z; hh[4*j+3] = t2.w;
    }

    // Restore invariant for next invocation: zero g_agg1 half-row; g_deg by q==1
    // (safe: the g_deg read above executes convergently before this store).
    {
        float4* z = (float4*)&g_agg1[(long long)n * INC + q * 16];
#pragma unroll
        for (int j = 0; j < 4; j++) z[j] = make_float4(0.f, 0.f, 0.f, 0.f);
        if (q == 1) g_deg[n] = 0.0f;
    }

    const float4* wl4 = (const float4*)swl;
    const float4* wr4 = (const float4*)swr;
    float oacc = 0.0f;
    int obase = q * 32;

#pragma unroll 1
    for (int oo = 0; oo < 32; oo++) {
        int o = obase + oo;
        float acc = 0.f;
#pragma unroll
        for (int j = 0; j < 16; j++) {
            float4 wl = wl4[o * 16 + j];
            float4 wr = wr4[o * 16 + j];
            acc += a[4*j+0]*wl.x + a[4*j+1]*wl.y + a[4*j+2]*wl.z + a[4*j+3]*wl.w;
            acc += hh[4*j+0]*wr.x + hh[4*j+1]*wr.y + hh[4*j+2]*wr.z + hh[4*j+3]*wr.w;
        }
        float val = fmaxf(acc * alpha[o] + beta[o], 0.0f);
        oacc += val * swo[o];
    }

    // Combine the two halves of the head dot-product (pair is in one warp)
    oacc += __shfl_xor_sync(0xFFFFFFFFu, oacc, 1);
    if (q == 0) out[n] = oacc + blin[0];
}

// ---------------------------------------------------------------------------
// Launch
// ---------------------------------------------------------------------------
extern "C" void kernel_launch(void* const* d_in, const int* in_sizes, int n_in,
                              void* d_out, int out_size) {
    const float* x   = (const float*)d_in[0];
    const int*   ei  = (const int*)d_in[1];   // int32 (jax x64 disabled)
    const int*   src = ei;
    const int*   dst = ei + EE;
    const float* W1l  = (const float*)d_in[2];
    const float* b1l  = (const float*)d_in[3];
    const float* W1r  = (const float*)d_in[4];
    const float* bn1g = (const float*)d_in[5];
    const float* bn1b = (const float*)d_in[6];
    const float* bn1m = (const float*)d_in[7];
    const float* bn1v = (const float*)d_in[8];
    const float* W2l  = (const float*)d_in[9];
    const float* b2l  = (const float*)d_in[10];
    const float* W2r  = (const float*)d_in[11];
    const float* bn2g = (const float*)d_in[12];
    const float* bn2b = (const float*)d_in[13];
    const float* bn2m = (const float*)d_in[14];
    const float* bn2v = (const float*)d_in[15];
    const float* Wlin = (const float*)d_in[16];
    const float* blin = (const float*)d_in[17];
    float* out = (float*)d_out;

    k_scatter1<<<(EE * 2 + 255) / 256, 256>>>(x, src, dst);
    k_layer1<<<(NN * 2 + 255) / 256, 256>>>(x, W1l, b1l, W1r,
                                            bn1g, bn1b, bn1m, bn1v);
    k_scatter2<<<(EE * 4 + 255) / 256, 256>>>(src, dst);
    k_layer2<<<(NN * 2 + 255) / 256, 256>>>(W2l, b2l, W2r,
                                            bn2g, bn2b, bn2m, bn2v,
                                            Wlin, blin, out);
}

// round 4
// speedup vs baseline: 1.8637x; 1.8637x over previous
#include <cuda_runtime.h>

#define NN   50000
#define EE   800000
#define INC  32
#define HIDC 64

// Scratch (device globals — zero-initialized at module load).
// Invariant: g_agg1 and g_deg are ZERO at entry of every kernel_launch call
// (k_layer2 restores them). g_agg2 is zeroed by k_layer1 before k_scatter2.
__device__ __align__(16) float g_deg[NN];
__device__ __align__(16) float g_agg1[NN * INC];
__device__ __align__(16) float g_agg2[NN * HIDC];
__device__ __align__(16) float g_h[NN * HIDC];

__device__ __forceinline__ void red_add_v4(float* p, float4 v) {
    asm volatile("red.global.add.v4.f32 [%0], {%1,%2,%3,%4};"
                 :: "l"(p), "f"(v.x), "f"(v.y), "f"(v.z), "f"(v.w)
                 : "memory");
}

// ---------------------------------------------------------------------------
// Scatter 1: agg1[dst, 0:32] += x[src, 0:32]; deg[dst] += 1   (8 thr/edge)
// ---------------------------------------------------------------------------
__global__ __launch_bounds__(256)
void k_scatter1(const float* __restrict__ x,
                const int* __restrict__ src,
                const int* __restrict__ dst) {
    int idx = blockIdx.x * blockDim.x + threadIdx.x;
    if (idx >= EE * 8) return;
    int e = idx >> 3;
    int q = idx & 7;
    int s = __ldg(&src[e]);
    int d = __ldg(&dst[e]);
    float4 v = __ldg((const float4*)x + (long long)s * 8 + q);
    red_add_v4(&g_agg1[(long long)d * INC + q * 4], v);
    if (q == 0) atomicAdd(&g_deg[d], 1.0f);
}

// ---------------------------------------------------------------------------
// Scatter 2: agg2[dst, 0:64] += h[src, 0:64]   (16 thr/edge)
// ---------------------------------------------------------------------------
__global__ __launch_bounds__(256)
void k_scatter2(const int* __restrict__ src,
                const int* __restrict__ dst) {
    int idx = blockIdx.x * blockDim.x + threadIdx.x;
    if (idx >= EE * 16) return;
    int e = idx >> 4;
    int q = idx & 15;
    int s = __ldg(&src[e]);
    int d = __ldg(&dst[e]);
    float4 v = __ldg((const float4*)g_h + (long long)s * 16 + q);
    red_add_v4(&g_agg2[(long long)d * HIDC + q * 4], v);
}

// ---------------------------------------------------------------------------
// Layer 1 as tiled GEMM: h[n][o] = relu(alpha1[o]*(in@Wcat)[n][o] + beta1[o])
//   in[n] = [ agg1[n]*dinv (32) | x[n] (32) ]  (K=64)
//   Wcat  = [ W1l ; W1r ]  ([k][o], direct copy)
// Block: 128 nodes x 64 outs, 128 threads, 8x8 register tile each.
// Also zeroes g_agg2 rows for scatter2.
// ---------------------------------------------------------------------------
#define L1_K   64
#define L1_PAD 65
// smem layout (bytes): SIN 128*65*4=33280 | SW 64*64*4=16384 | SDINV 512 | AB 512
#define L1_SIN   0
#define L1_SW    33280
#define L1_SDINV (33280 + 16384)
#define L1_ALPHA (L1_SDINV + 512)
#define L1_BETA  (L1_ALPHA + 256)
#define L1_SMEM  (L1_BETA + 256)

__global__ __launch_bounds__(128)
void k_layer1(const float* __restrict__ x,
              const float* __restrict__ W1l, const float* __restrict__ b1l,
              const float* __restrict__ W1r,
              const float* __restrict__ g1, const float* __restrict__ bb1,
              const float* __restrict__ m1, const float* __restrict__ v1) {
    extern __shared__ char smem_raw[];
    float* SIN  = (float*)(smem_raw + L1_SIN);
    float* SW   = (float*)(smem_raw + L1_SW);
    float* SDI  = (float*)(smem_raw + L1_SDINV);
    float* SAL  = (float*)(smem_raw + L1_ALPHA);
    float* SBE  = (float*)(smem_raw + L1_BETA);

    int t = threadIdx.x;
    int nb = blockIdx.x * 128;

    // Phase 0: dinv per node; zero g_agg2 row for this node
    {
        int n = nb + t;
        int nc = n < NN ? n : NN - 1;
        SDI[t] = 1.0f / fmaxf(g_deg[nc], 1.0f);
        if (n < NN) {
            float4* z = (float4*)&g_agg2[(long long)n * HIDC];
            float4 zero = make_float4(0.f, 0.f, 0.f, 0.f);
#pragma unroll
            for (int j = 0; j < 16; j++) z[j] = zero;
        }
    }
    __syncthreads();

    // Phase 1: stage inputs (transpose-free node-major, pad 65) + weights
#pragma unroll
    for (int it = 0; it < 16; it++) {
        int f = t + 128 * it;           // float4 id, [0, 2048)
        int m = f >> 4;
        int c = f & 15;
        int n = nb + m; int nc = n < NN ? n : NN - 1;
        float4 v; int k;
        if (c < 8) {
            v = __ldg((const float4*)&g_agg1[(long long)nc * INC] + c);
            float di = SDI[m];
            v.x *= di; v.y *= di; v.z *= di; v.w *= di;
            k = c * 4;
        } else {
            v = __ldg((const float4*)&x[(long long)nc * INC] + (c - 8));
            k = 32 + (c - 8) * 4;
        }
        float* dst = &SIN[m * L1_PAD + k];
        dst[0] = v.x; dst[1] = v.y; dst[2] = v.z; dst[3] = v.w;
    }
#pragma unroll
    for (int it = 0; it < 8; it++) {
        int f4 = t + 128 * it;          // [0, 1024)
        float4 v = (f4 < 512) ? __ldg((const float4*)W1l + f4)
                              : __ldg((const float4*)W1r + (f4 - 512));
        ((float4*)SW)[f4] = v;
    }
    if (t < HIDC) {
        float a = g1[t] * rsqrtf(v1[t] + 1e-5f);
        SAL[t] = a;
        SBE[t] = (b1l[t] - m1[t]) * a + bb1[t];
    }
    __syncthreads();

    // Phase 2: 8x8 register-tile GEMM
    int tn = t & 7;          // output group
    int tm = t >> 3;         // node group (0..15)
    const float* sinb = &SIN[(tm * 8) * L1_PAD];
    const float4* sw4 = (const float4*)SW;

    float acc[64];
#pragma unroll
    for (int i = 0; i < 64; i++) acc[i] = 0.f;

#pragma unroll 4
    for (int k = 0; k < L1_K; k++) {
        float av[8];
#pragma unroll
        for (int i = 0; i < 8; i++) av[i] = sinb[i * L1_PAD + k];
        float4 w0 = sw4[k * 16 + tn * 2];
        float4 w1 = sw4[k * 16 + tn * 2 + 1];
#pragma unroll
        for (int i = 0; i < 8; i++) {
            acc[i*8+0] += av[i] * w0.x;
            acc[i*8+1] += av[i] * w0.y;
            acc[i*8+2] += av[i] * w0.z;
            acc[i*8+3] += av[i] * w0.w;
            acc[i*8+4] += av[i] * w1.x;
            acc[i*8+5] += av[i] * w1.y;
            acc[i*8+6] += av[i] * w1.z;
            acc[i*8+7] += av[i] * w1.w;
        }
    }

    // Epilogue: BN + ReLU, store h
    float al[8], be[8];
#pragma unroll
    for (int j = 0; j < 8; j++) { al[j] = SAL[tn*8+j]; be[j] = SBE[tn*8+j]; }
#pragma unroll
    for (int i = 0; i < 8; i++) {
        int n = nb + tm * 8 + i;
        if (n < NN) {
            float r[8];
#pragma unroll
            for (int j = 0; j < 8; j++)
                r[j] = fmaxf(acc[i*8+j] * al[j] + be[j], 0.f);
            float4* hv = (float4*)&g_h[(long long)n * HIDC + tn * 8];
            hv[0] = make_float4(r[0], r[1], r[2], r[3]);
            hv[1] = make_float4(r[4], r[5], r[6], r[7]);
        }
    }
}

// ---------------------------------------------------------------------------
// Layer 2 + head as tiled GEMM:
//   h2[n][o] = relu(alpha2[o]*(in@Wcat)[n][o] + beta2[o]);  out[n] = h2@Wlin+b
//   in[n] = [ agg2[n]*dinv (64) | h[n] (64) ]  (K=128)
// Also restores g_agg1/g_deg to zero for the next invocation.
// ---------------------------------------------------------------------------
#define L2_K   128
#define L2_PAD 129
// smem: SIN 128*129*4=66048 | SW 128*64*4=32768 | SDINV 512 | A/B/O 768
#define L2_SIN   0
#define L2_SW    66048
#define L2_SDINV (66048 + 32768)
#define L2_ALPHA (L2_SDINV + 512)
#define L2_BETA  (L2_ALPHA + 256)
#define L2_SWO   (L2_BETA + 256)
#define L2_SMEM  (L2_SWO + 256)

__global__ __launch_bounds__(128)
void k_layer2(const float* __restrict__ W2l, const float* __restrict__ b2l,
              const float* __restrict__ W2r,
              const float* __restrict__ g2, const float* __restrict__ bb2,
              const float* __restrict__ m2, const float* __restrict__ v2,
              const float* __restrict__ Wlin, const float* __restrict__ blin,
              float* __restrict__ out) {
    extern __shared__ char smem_raw[];
    float* SIN = (float*)(smem_raw + L2_SIN);
    float* SW  = (float*)(smem_raw + L2_SW);
    float* SDI = (float*)(smem_raw + L2_SDINV);
    float* SAL = (float*)(smem_raw + L2_ALPHA);
    float* SBE = (float*)(smem_raw + L2_BETA);
    float* SWO = (float*)(smem_raw + L2_SWO);

    int t = threadIdx.x;
    int nb = blockIdx.x * 128;

    // Phase 0: dinv (reads deg), then restore invariants (zero agg1 + deg)
    {
        int n = nb + t;
        int nc = n < NN ? n : NN - 1;
        SDI[t] = 1.0f / fmaxf(g_deg[nc], 1.0f);
        if (n < NN) {
            float4* z = (float4*)&g_agg1[(long long)n * INC];
            float4 zero = make_float4(0.f, 0.f, 0.f, 0.f);
#pragma unroll
            for (int j = 0; j < 8; j++) z[j] = zero;
            g_deg[n] = 0.0f;
        }
    }
    __syncthreads();

    // Phase 1: stage inputs + weights
#pragma unroll
    for (int it = 0; it < 32; it++) {
        int f = t + 128 * it;           // float4 id, [0, 4096)
        int m = f >> 5;
        int c = f & 31;
        int n = nb + m; int nc = n < NN ? n : NN - 1;
        float4 v; int k;
        if (c < 16) {
            v = __ldg((const float4*)&g_agg2[(long long)nc * HIDC] + c);
            float di = SDI[m];
            v.x *= di; v.y *= di; v.z *= di; v.w *= di;
            k = c * 4;
        } else {
            v = __ldg((const float4*)&g_h[(long long)nc * HIDC] + (c - 16));
            k = 64 + (c - 16) * 4;
        }
        float* dst = &SIN[m * L2_PAD + k];
        dst[0] = v.x; dst[1] = v.y; dst[2] = v.z; dst[3] = v.w;
    }
#pragma unroll
    for (int it = 0; it < 16; it++) {
        int f4 = t + 128 * it;          // [0, 2048)
        float4 v = (f4 < 1024) ? __ldg((const float4*)W2l + f4)
                               : __ldg((const float4*)W2r + (f4 - 1024));
        ((float4*)SW)[f4] = v;
    }
    if (t < HIDC) {
        float a = g2[t] * rsqrtf(v2[t] + 1e-5f);
        SAL[t] = a;
        SBE[t] = (b2l[t] - m2[t]) * a + bb2[t];
        SWO[t] = Wlin[t];
    }
    __syncthreads();

    // Phase 2: 8x8 register-tile GEMM
    int tn = t & 7;
    int tm = t >> 3;
    const float* sinb = &SIN[(tm * 8) * L2_PAD];
    const float4* sw4 = (const float4*)SW;

    float acc[64];
#pragma unroll
    for (int i = 0; i < 64; i++) acc[i] = 0.f;

#pragma unroll 4
    for (int k = 0; k < L2_K; k++) {
        float av[8];
#pragma unroll
        for (int i = 0; i < 8; i++) av[i] = sinb[i * L2_PAD + k];
        float4 w0 = sw4[k * 16 + tn * 2];
        float4 w1 = sw4[k * 16 + tn * 2 + 1];
#pragma unroll
        for (int i = 0; i < 8; i++) {
            acc[i*8+0] += av[i] * w0.x;
            acc[i*8+1] += av[i] * w0.y;
            acc[i*8+2] += av[i] * w0.z;
            acc[i*8+3] += av[i] * w0.w;
            acc[i*8+4] += av[i] * w1.x;
            acc[i*8+5] += av[i] * w1.y;
            acc[i*8+6] += av[i] * w1.z;
            acc[i*8+7] += av[i] * w1.w;
        }
    }

    // Epilogue: BN + ReLU + head dot, reduce across the 8 tn lanes (same warp)
    float part[8];
#pragma unroll
    for (int i = 0; i < 8; i++) part[i] = 0.f;
#pragma unroll
    for (int j = 0; j < 8; j++) {
        int o = tn * 8 + j;
        float a = SAL[o], b = SBE[o], so = SWO[o];
#pragma unroll
        for (int i = 0; i < 8; i++) {
            float val = fmaxf(acc[i*8+j] * a + b, 0.f);
            part[i] += val * so;
        }
    }
#pragma unroll
    for (int i = 0; i < 8; i++) {
        part[i] += __shfl_xor_sync(0xFFFFFFFFu, part[i], 1);
        part[i] += __shfl_xor_sync(0xFFFFFFFFu, part[i], 2);
        part[i] += __shfl_xor_sync(0xFFFFFFFFu, part[i], 4);
    }
    if (tn == 0) {
        float b0 = __ldg(&blin[0]);
#pragma unroll
        for (int i = 0; i < 8; i++) {
            int n = nb + tm * 8 + i;
            if (n < NN) out[n] = part[i] + b0;
        }
    }
}

// ---------------------------------------------------------------------------
// Launch
// ---------------------------------------------------------------------------
extern "C" void kernel_launch(void* const* d_in, const int* in_sizes, int n_in,
                              void* d_out, int out_size) {
    const float* x   = (const float*)d_in[0];
    const int*   ei  = (const int*)d_in[1];   // int32 (jax x64 disabled)
    const int*   src = ei;
    const int*   dst = ei + EE;
    const float* W1l  = (const float*)d_in[2];
    const float* b1l  = (const float*)d_in[3];
    const float* W1r  = (const float*)d_in[4];
    const float* bn1g = (const float*)d_in[5];
    const float* bn1b = (const float*)d_in[6];
    const float* bn1m = (const float*)d_in[7];
    const float* bn1v = (const float*)d_in[8];
    const float* W2l  = (const float*)d_in[9];
    const float* b2l  = (const float*)d_in[10];
    const float* W2r  = (const float*)d_in[11];
    const float* bn2g = (const float*)d_in[12];
    const float* bn2b = (const float*)d_in[13];
    const float* bn2m = (const float*)d_in[14];
    const float* bn2v = (const float*)d_in[15];
    const float* Wlin = (const float*)d_in[16];
    const float* blin = (const float*)d_in[17];
    float* out = (float*)d_out;

    // Opt into >48KB dynamic smem (attribute set is not a stream op; capture-safe)
    cudaFuncSetAttribute(k_layer1, cudaFuncAttributeMaxDynamicSharedMemorySize, L1_SMEM);
    cudaFuncSetAttribute(k_layer2, cudaFuncAttributeMaxDynamicSharedMemorySize, L2_SMEM);

    int nblk = (NN + 127) / 128;   // 391

    k_scatter1<<<(EE * 8) / 256, 256>>>(x, src, dst);
    k_layer1<<<nblk, 128, L1_SMEM>>>(x, W1l, b1l, W1r, bn1g, bn1b, bn1m, bn1v);
    k_scatter2<<<(EE * 16) / 256, 256>>>(src, dst);
    k_layer2<<<nblk, 128, L2_SMEM>>>(W2l, b2l, W2r, bn2g, bn2b, bn2m, bn2v,
                                     Wlin, blin, out);
}

// round 5
// speedup vs baseline: 1.9557x; 1.0493x over previous
#include <cuda_runtime.h>

#define NN   50000
#define EE   800000
#define INC  32
#define HIDC 64
#define SCAN_BLOCKS 196          // ceil(NN/256)

// -------------------- device scratch (no allocation allowed) ----------------
__device__ __align__(16) int   g_cnt[NN];        // per-node degree (histogram)
__device__ __align__(16) int   g_cursor[NN];     // CSR fill cursors
__device__ __align__(16) int   g_part[NN];       // in-block exclusive prefix
__device__ __align__(16) int   g_bsum[256];      // per-block totals
__device__ __align__(16) int   g_bscan[256];     // exclusive block offsets
__device__ __align__(16) int   g_csr[EE];        // src ids grouped by dst
__device__ __align__(16) float g_agg1[NN * INC]; // mean-agg of x   (normalized)
__device__ __align__(16) float g_agg2[NN * HIDC];// mean-agg of h   (normalized)
__device__ __align__(16) float g_h[NN * HIDC];   // layer-1 output

// -------------------- f32x2 packed math helpers -----------------------------
__device__ __forceinline__ unsigned long long pack2(float lo, float hi) {
    unsigned long long r;
    asm("mov.b64 %0, {%1, %2};" : "=l"(r) : "f"(lo), "f"(hi));
    return r;
}
__device__ __forceinline__ void unpack2(float& lo, float& hi, unsigned long long v) {
    asm("mov.b64 {%0, %1}, %2;" : "=f"(lo), "=f"(hi) : "l"(v));
}
#define FMA2(d, a, b) asm("fma.rn.f32x2 %0, %1, %2, %0;" : "+l"(d) : "l"(a), "l"(b))

// ============================================================================
// CSR build
// ============================================================================
__global__ void k_zero0() {
    int i = blockIdx.x * blockDim.x + threadIdx.x;
    if (i < NN / 4) {
        ((int4*)g_cnt)[i]    = make_int4(0, 0, 0, 0);
        ((int4*)g_cursor)[i] = make_int4(0, 0, 0, 0);
    }
}

__global__ void k_hist(const int* __restrict__ dst) {
    int e = blockIdx.x * blockDim.x + threadIdx.x;
    if (e < EE) atomicAdd(&g_cnt[__ldg(&dst[e])], 1);
}

// Per-block exclusive scan of g_cnt (256-wide Hillis-Steele)
__global__ __launch_bounds__(256) void k_scan1() {
    __shared__ int s[256];
    int t = threadIdx.x;
    int i = blockIdx.x * 256 + t;
    int v = (i < NN) ? g_cnt[i] : 0;
    s[t] = v;
    __syncthreads();
#pragma unroll
    for (int off = 1; off < 256; off <<= 1) {
        int add = (t >= off) ? s[t - off] : 0;
        __syncthreads();
        s[t] += add;
        __syncthreads();
    }
    if (i < NN) g_part[i] = s[t] - v;      // exclusive
    if (t == 255) g_bsum[blockIdx.x] = s[255];
}

// Scan of the block totals (single block)
__global__ __launch_bounds__(256) void k_scan2() {
    __shared__ int s[256];
    int t = threadIdx.x;
    int v = (t < SCAN_BLOCKS) ? g_bsum[t] : 0;
    s[t] = v;
    __syncthreads();
#pragma unroll
    for (int off = 1; off < 256; off <<= 1) {
        int add = (t >= off) ? s[t - off] : 0;
        __syncthreads();
        s[t] += add;
        __syncthreads();
    }
    g_bscan[t] = s[t] - v;                 // exclusive
}

__global__ void k_fill(const int* __restrict__ src, const int* __restrict__ dst) {
    int e = blockIdx.x * blockDim.x + threadIdx.x;
    if (e >= EE) return;
    int d = __ldg(&dst[e]);
    int base = g_part[d] + g_bscan[d >> 8];
    int slot = base + atomicAdd(&g_cursor[d], 1);
    g_csr[slot] = __ldg(&src[e]);
}

// ============================================================================
// Aggregations: warp per node, CSR gather, write normalized mean once.
// ============================================================================
__global__ __launch_bounds__(256) void k_agg1(const float* __restrict__ x) {
    int gt = blockIdx.x * blockDim.x + threadIdx.x;
    int n = gt >> 5, lane = gt & 31;
    if (n >= NN) return;
    int base = g_part[n] + g_bscan[n >> 8];
    int deg  = g_cnt[n];
    float acc = 0.f;
    int j = 0;
    for (; j + 1 < deg; j += 2) {
        int s0 = __ldg(&g_csr[base + j]);
        int s1 = __ldg(&g_csr[base + j + 1]);
        acc += __ldg(&x[(long long)s0 * INC + lane]);
        acc += __ldg(&x[(long long)s1 * INC + lane]);
    }
    if (j < deg) {
        int s0 = __ldg(&g_csr[base + j]);
        acc += __ldg(&x[(long long)s0 * INC + lane]);
    }
    float dinv = 1.0f / fmaxf((float)deg, 1.0f);
    g_agg1[(long long)n * INC + lane] = acc * dinv;
}

__global__ __launch_bounds__(256) void k_agg2() {
    int gt = blockIdx.x * blockDim.x + threadIdx.x;
    int n = gt >> 5, lane = gt & 31;
    if (n >= NN) return;
    int base = g_part[n] + g_bscan[n >> 8];
    int deg  = g_cnt[n];
    const float2* h2 = (const float2*)g_h;
    float2 acc = make_float2(0.f, 0.f);
    int j = 0;
    for (; j + 1 < deg; j += 2) {
        int s0 = __ldg(&g_csr[base + j]);
        int s1 = __ldg(&g_csr[base + j + 1]);
        float2 v0 = __ldg(&h2[(long long)s0 * 32 + lane]);
        float2 v1 = __ldg(&h2[(long long)s1 * 32 + lane]);
        acc.x += v0.x + v1.x;
        acc.y += v0.y + v1.y;
    }
    if (j < deg) {
        int s0 = __ldg(&g_csr[base + j]);
        float2 v0 = __ldg(&h2[(long long)s0 * 32 + lane]);
        acc.x += v0.x;
        acc.y += v0.y;
    }
    float dinv = 1.0f / fmaxf((float)deg, 1.0f);
    acc.x *= dinv; acc.y *= dinv;
    ((float2*)g_agg2)[(long long)n * 32 + lane] = acc;
}

// ============================================================================
// Layer 1 GEMM: h[n][o] = relu(a1[o]*([agg1 | x] @ [W1l;W1r])[n][o] + b1[o])
// 128 nodes x 64 outs per block, 256 threads, 4x8 tile (f32x2 accumulators).
// ============================================================================
#define L1_PAD   65
#define L1_SIN   0
#define L1_SW    (128 * L1_PAD * 4)          // 33280
#define L1_ALPHA (L1_SW + 64 * 64 * 4)       // +16384
#define L1_BETA  (L1_ALPHA + 256)
#define L1_SMEM  (L1_BETA + 256)             // 50176

__global__ __launch_bounds__(256)
void k_layer1(const float* __restrict__ x,
              const float* __restrict__ W1l, const float* __restrict__ b1l,
              const float* __restrict__ W1r,
              const float* __restrict__ g1, const float* __restrict__ bb1,
              const float* __restrict__ m1, const float* __restrict__ v1) {
    extern __shared__ char smem_raw[];
    float* SIN = (float*)(smem_raw + L1_SIN);
    float* SW  = (float*)(smem_raw + L1_SW);
    float* SAL = (float*)(smem_raw + L1_ALPHA);
    float* SBE = (float*)(smem_raw + L1_BETA);

    int t = threadIdx.x;
    int nb = blockIdx.x * 128;

    // Stage inputs node-major [m][k], K=64 = [agg1(32) | x(32)]
#pragma unroll
    for (int it = 0; it < 8; it++) {
        int f = t + 256 * it;            // float4 id [0,2048)
        int m = f >> 4, c = f & 15;
        int n = nb + m; int nc = n < NN ? n : NN - 1;
        float4 v; int k;
        if (c < 8) { v = __ldg((const float4*)&g_agg1[(long long)nc * INC] + c); k = c * 4; }
        else       { v = __ldg((const float4*)&x[(long long)nc * INC] + (c - 8)); k = 32 + (c - 8) * 4; }
        float* dp = &SIN[m * L1_PAD + k];
        dp[0] = v.x; dp[1] = v.y; dp[2] = v.z; dp[3] = v.w;
    }
#pragma unroll
    for (int it = 0; it < 4; it++) {
        int f4 = t + 256 * it;           // [0,1024)
        float4 v = (f4 < 512) ? __ldg((const float4*)W1l + f4)
                              : __ldg((const float4*)W1r + (f4 - 512));
        ((float4*)SW)[f4] = v;
    }
    if (t < HIDC) {
        float a = g1[t] * rsqrtf(v1[t] + 1e-5f);
        SAL[t] = a;
        SBE[t] = (b1l[t] - m1[t]) * a + bb1[t];
    }
    __syncthreads();

    int tn = t & 7, tm = t >> 3;         // tm in [0,32)
    const float* sinb = &SIN[(tm * 4) * L1_PAD];
    const ulonglong2* swu = (const ulonglong2*)SW;   // row k = 16 ull2

    unsigned long long acc[16];          // [node i][pair p] = acc[i*4+p]
#pragma unroll
    for (int i = 0; i < 16; i++) acc[i] = 0ull;

#pragma unroll 4
    for (int k = 0; k < 64; k++) {
        unsigned long long ad[4];
#pragma unroll
        for (int i = 0; i < 4; i++) {
            float av = sinb[i * L1_PAD + k];
            ad[i] = pack2(av, av);
        }
        ulonglong2 wA = swu[k * 16 + tn * 2];
        ulonglong2 wB = swu[k * 16 + tn * 2 + 1];
#pragma unroll
        for (int i = 0; i < 4; i++) {
            FMA2(acc[i*4+0], ad[i], wA.x);
            FMA2(acc[i*4+1], ad[i], wA.y);
            FMA2(acc[i*4+2], ad[i], wB.x);
            FMA2(acc[i*4+3], ad[i], wB.y);
        }
    }

    float al[8], be[8];
#pragma unroll
    for (int j = 0; j < 8; j++) { al[j] = SAL[tn*8+j]; be[j] = SBE[tn*8+j]; }
#pragma unroll
    for (int i = 0; i < 4; i++) {
        int n = nb + tm * 4 + i;
        if (n < NN) {
            float r[8];
#pragma unroll
            for (int p = 0; p < 4; p++) unpack2(r[2*p], r[2*p+1], acc[i*4+p]);
#pragma unroll
            for (int j = 0; j < 8; j++) r[j] = fmaxf(r[j] * al[j] + be[j], 0.f);
            float4* hv = (float4*)&g_h[(long long)n * HIDC + tn * 8];
            hv[0] = make_float4(r[0], r[1], r[2], r[3]);
            hv[1] = make_float4(r[4], r[5], r[6], r[7]);
        }
    }
}

// ============================================================================
// Layer 2 + head: h2 = relu(bn2([agg2 | h] @ [W2l;W2r])); out = h2 @ Wlin + b
// ============================================================================
#define L2_PAD   129
#define L2_SIN   0
#define L2_SW    (128 * L2_PAD * 4)          // 66048
#define L2_ALPHA (L2_SW + 128 * 64 * 4)      // +32768
#define L2_BETA  (L2_ALPHA + 256)
#define L2_SWO   (L2_BETA + 256)
#define L2_SMEM  (L2_SWO + 256)              // 99584

__global__ __launch_bounds__(256)
void k_layer2(const float* __restrict__ W2l, const float* __restrict__ b2l,
              const float* __restrict__ W2r,
              const float* __restrict__ g2, const float* __restrict__ bb2,
              const float* __restrict__ m2, const float* __restrict__ v2,
              const float* __restrict__ Wlin, const float* __restrict__ blin,
              float* __restrict__ out) {
    extern __shared__ char smem_raw[];
    float* SIN = (float*)(smem_raw + L2_SIN);
    float* SW  = (float*)(smem_raw + L2_SW);
    float* SAL = (float*)(smem_raw + L2_ALPHA);
    float* SBE = (float*)(smem_raw + L2_BETA);
    float* SWO = (float*)(smem_raw + L2_SWO);

    int t = threadIdx.x;
    int nb = blockIdx.x * 128;

    // Stage inputs node-major [m][k], K=128 = [agg2(64) | h(64)]
#pragma unroll
    for (int it = 0; it < 16; it++) {
        int f = t + 256 * it;            // float4 id [0,4096)
        int m = f >> 5, c = f & 31;
        int n = nb + m; int nc = n < NN ? n : NN - 1;
        float4 v; int k;
        if (c < 16) { v = __ldg((const float4*)&g_agg2[(long long)nc * HIDC] + c); k = c * 4; }
        else        { v = __ldg((const float4*)&g_h[(long long)nc * HIDC] + (c - 16)); k = 64 + (c - 16) * 4; }
        float* dp = &SIN[m * L2_PAD + k];
        dp[0] = v.x; dp[1] = v.y; dp[2] = v.z; dp[3] = v.w;
    }
#pragma unroll
    for (int it = 0; it < 8; it++) {
        int f4 = t + 256 * it;           // [0,2048)
        float4 v = (f4 < 1024) ? __ldg((const float4*)W2l + f4)
                               : __ldg((const float4*)W2r + (f4 - 1024));
        ((float4*)SW)[f4] = v;
    }
    if (t < HIDC) {
        float a = g2[t] * rsqrtf(v2[t] + 1e-5f);
        SAL[t] = a;
        SBE[t] = (b2l[t] - m2[t]) * a + bb2[t];
        SWO[t] = Wlin[t];
    }
    __syncthreads();

    int tn = t & 7, tm = t >> 3;
    const float* sinb = &SIN[(tm * 4) * L2_PAD];
    const ulonglong2* swu = (const ulonglong2*)SW;

    unsigned long long acc[16];
#pragma unroll
    for (int i = 0; i < 16; i++) acc[i] = 0ull;

#pragma unroll 4
    for (int k = 0; k < 128; k++) {
        unsigned long long ad[4];
#pragma unroll
        for (int i = 0; i < 4; i++) {
            float av = sinb[i * L2_PAD + k];
            ad[i] = pack2(av, av);
        }
        ulonglong2 wA = swu[k * 16 + tn * 2];
        ulonglong2 wB = swu[k * 16 + tn * 2 + 1];
#pragma unroll
        for (int i = 0; i < 4; i++) {
            FMA2(acc[i*4+0], ad[i], wA.x);
            FMA2(acc[i*4+1], ad[i], wA.y);
            FMA2(acc[i*4+2], ad[i], wB.x);
            FMA2(acc[i*4+3], ad[i], wB.y);
        }
    }

    // BN + ReLU + head dot; reduce across the 8 tn lanes of each node row.
    float al[8], be[8], wo[8];
#pragma unroll
    for (int j = 0; j < 8; j++) {
        al[j] = SAL[tn*8+j]; be[j] = SBE[tn*8+j]; wo[j] = SWO[tn*8+j];
    }
    float part[4];
#pragma unroll
    for (int i = 0; i < 4; i++) {
        float r[8];
#pragma unroll
        for (int p = 0; p < 4; p++) unpack2(r[2*p], r[2*p+1], acc[i*4+p]);
        float s = 0.f;
#pragma unroll
        for (int j = 0; j < 8; j++)
            s += fmaxf(r[j] * al[j] + be[j], 0.f) * wo[j];
        part[i] = s;
    }
#pragma unroll
    for (int i = 0; i < 4; i++) {
        part[i] += __shfl_xor_sync(0xFFFFFFFFu, part[i], 1);
        part[i] += __shfl_xor_sync(0xFFFFFFFFu, part[i], 2);
        part[i] += __shfl_xor_sync(0xFFFFFFFFu, part[i], 4);
    }
    if (tn == 0) {
        float b0 = __ldg(&blin[0]);
#pragma unroll
        for (int i = 0; i < 4; i++) {
            int n = nb + tm * 4 + i;
            if (n < NN) out[n] = part[i] + b0;
        }
    }
}

// ============================================================================
// Launch
// ============================================================================
extern "C" void kernel_launch(void* const* d_in, const int* in_sizes, int n_in,
                              void* d_out, int out_size) {
    const float* x   = (const float*)d_in[0];
    const int*   ei  = (const int*)d_in[1];   // int32 (jax x64 disabled)
    const int*   src = ei;
    const int*   dst = ei + EE;
    const float* W1l  = (const float*)d_in[2];
    const float* b1l  = (const float*)d_in[3];
    const float* W1r  = (const float*)d_in[4];
    const float* bn1g = (const float*)d_in[5];
    const float* bn1b = (const float*)d_in[6];
    const float* bn1m = (const float*)d_in[7];
    const float* bn1v = (const float*)d_in[8];
    const float* W2l  = (const float*)d_in[9];
    const float* b2l  = (const float*)d_in[10];
    const float* W2r  = (const float*)d_in[11];
    const float* bn2g = (const float*)d_in[12];
    const float* bn2b = (const float*)d_in[13];
    const float* bn2m = (const float*)d_in[14];
    const float* bn2v = (const float*)d_in[15];
    const float* Wlin = (const float*)d_in[16];
    const float* blin = (const float*)d_in[17];
    float* out = (float*)d_out;

    cudaFuncSetAttribute(k_layer1, cudaFuncAttributeMaxDynamicSharedMemorySize, L1_SMEM);
    cudaFuncSetAttribute(k_layer2, cudaFuncAttributeMaxDynamicSharedMemorySize, L2_SMEM);

    // CSR build
    k_zero0<<<(NN / 4 + 255) / 256, 256>>>();
    k_hist <<<(EE + 255) / 256, 256>>>(dst);
    k_scan1<<<SCAN_BLOCKS, 256>>>();
    k_scan2<<<1, 256>>>();
    k_fill <<<(EE + 255) / 256, 256>>>(src, dst);

    int nblk = (NN + 127) / 128;             // 391
    int ablk = (NN * 32 + 255) / 256;        // 6250

    k_agg1 <<<ablk, 256>>>(x);
    k_layer1<<<nblk, 256, L1_SMEM>>>(x, W1l, b1l, W1r, bn1g, bn1b, bn1m, bn1v);
    k_agg2 <<<ablk, 256>>>();
    k_layer2<<<nblk, 256, L2_SMEM>>>(W2l, b2l, W2r, bn2g, bn2b, bn2m, bn2v,
                                     Wlin, blin, out);
}